// round 11
// baseline (speedup 1.0000x reference)
#include <cuda_runtime.h>
#include <cuda_bf16.h>
#include <cstdint>
#include <math.h>

#define T_SEQ 2048
#define BATCH 2
#define EMB   1024
#define NH    16
#define DH    64
#define NTOK  (BATCH * T_SEQ)

__device__ float g_Q[(size_t)NTOK * EMB];
__device__ float g_K[(size_t)NTOK * EMB];
__device__ float g_V[(size_t)NTOK * EMB];
__device__ uint32_t g_A2[(size_t)3 * NTOK * EMB];   // tf32 activations
__device__ uint32_t g_B2[(size_t)4 * EMB  * EMB];   // tf32 weights (q,k,v,o)

__device__ __forceinline__ uint32_t smem_u32(const void* p) {
    uint32_t a;
    asm("{ .reg .u64 t; cvta.to.shared.u64 t, %1; cvt.u32.u64 %0, t; }" : "=r"(a) : "l"(p));
    return a;
}
#define CP16(dst, src) \
    asm volatile("cp.async.cg.shared.global [%0], [%1], 16;" :: "r"(dst), "l"(src) : "memory")
#define CP_COMMIT() asm volatile("cp.async.commit_group;" ::: "memory")
#define CP_WAIT1()  asm volatile("cp.async.wait_group 1;" ::: "memory")

__device__ __forceinline__ uint32_t f2tf32(float x) {
    uint32_t u;
    asm("cvt.rna.tf32.f32 %0, %1;" : "=r"(u) : "f"(x));
    return u;
}
#define MMA_TF32(c, a0, a1, a2, a3, b0, b1)                                 \
    asm volatile("mma.sync.aligned.m16n8k8.row.col.f32.tf32.tf32.f32 "     \
        "{%0,%1,%2,%3}, {%4,%5,%6,%7}, {%8,%9}, {%0,%1,%2,%3};"            \
        : "+f"((c)[0]), "+f"((c)[1]), "+f"((c)[2]), "+f"((c)[3])           \
        : "r"(a0), "r"(a1), "r"(a2), "r"(a3), "r"(b0), "r"(b1))

// ---------------------------------------------------------------------------
// tf32 converts: acts (q,k,v batched), weights (q,k,v,o batched).
// ---------------------------------------------------------------------------
__global__ void conv_act(const float* __restrict__ q, const float* __restrict__ k,
                         const float* __restrict__ v)
{
    const int z = blockIdx.x >> 12;
    const float* X = (z == 0) ? q : (z == 1) ? k : v;
    uint32_t* Y = g_A2 + (size_t)z * NTOK * EMB;
    const int idx = (blockIdx.x & 4095) * 256 + threadIdx.x;
    float4 f = ((const float4*)X)[idx];
    uint4 u;
    u.x = f2tf32(f.x); u.y = f2tf32(f.y); u.z = f2tf32(f.z); u.w = f2tf32(f.w);
    ((uint4*)Y)[idx] = u;
}

__global__ void conv_wgt4(const float* __restrict__ Wq, const float* __restrict__ Wk,
                          const float* __restrict__ Wv, const float* __restrict__ Wo)
{
    const int z = blockIdx.x >> 10;
    const float* W = (z == 0) ? Wq : (z == 1) ? Wk : (z == 2) ? Wv : Wo;
    uint32_t* Y = g_B2 + (size_t)z * EMB * EMB;
    const int idx = (blockIdx.x & 1023) * 256 + threadIdx.x;
    float4 f = ((const float4*)W)[idx];
    uint4 u;
    u.x = f2tf32(f.x); u.y = f2tf32(f.y); u.z = f2tf32(f.z); u.w = f2tf32(f.w);
    ((uint4*)Y)[idx] = u;
}

// ---------------------------------------------------------------------------
// tf32 mma.sync GEMM (unchanged core): 128x128, BKC=32, 3-stage cp.async.
// BATCHED=1: z = blockIdx.z (QKV). BATCHED=0: A z=0, B z=3 (O-projection).
// ---------------------------------------------------------------------------
#define BKC 32
#define NCH (EMB / BKC)
#define ROWB 144
#define TILEB (128 * ROWB)
#define STAGEB (2 * TILEB)
#define NSTG 3
#define SMEM_GEMM (NSTG * STAGEB)

template <int BATCHED>
__global__ void __launch_bounds__(256, 2) gemm_kernel(float* __restrict__ Yp)
{
    extern __shared__ char smem[];
    const int t = threadIdx.x;
    const int wid = t >> 5, lane = t & 31;
    const int wm = wid & 1;
    const int wn = wid >> 1;
    const int m0 = blockIdx.y * 128;
    const int n0 = blockIdx.x * 128;
    const int zA = BATCHED ? blockIdx.z : 0;
    const int zB = BATCHED ? blockIdx.z : 3;

    const uint32_t* Ag = g_A2 + (size_t)zA * NTOK * EMB + (size_t)m0 * EMB;
    const uint32_t* Bg = g_B2 + (size_t)zB * EMB  * EMB + (size_t)n0 * EMB;

    float acc[4][4][4];
#pragma unroll
    for (int mi = 0; mi < 4; mi++)
#pragma unroll
        for (int ni = 0; ni < 4; ni++)
#pragma unroll
            for (int d = 0; d < 4; d++) acc[mi][ni][d] = 0.f;

    auto load_stage = [&](int ch, int stg) {
        char* base = smem + stg * STAGEB;
        const size_t koff = (size_t)ch * BKC;
#pragma unroll
        for (int q = 0; q < 8; q++) {
            const int s = t + q * 256;
            const int tile = s >> 10;
            const int r = (s >> 3) & 127;
            const int ks = s & 7;
            const uint32_t dst = smem_u32(base + tile * TILEB + r * ROWB + ks * 16);
            const uint32_t* src = (tile ? Bg : Ag) + (size_t)r * EMB + koff + ks * 4;
            CP16(dst, src);
        }
        CP_COMMIT();
    };

    load_stage(0, 0);
    load_stage(1, 1);

    const int ar = (lane & 7) + ((lane >> 3) & 1) * 8;
    const int ac4 = ((lane >> 4) & 1) * 4;
    const int br = (lane & 7) + ((lane >> 4) & 1) * 8;
    const int bc4 = ((lane >> 3) & 1) * 4;

    for (int ch = 0; ch < NCH; ch++) {
        const int stg = ch % NSTG;
        CP_WAIT1();
        __syncthreads();
        if (ch + 2 < NCH) load_stage(ch + 2, (ch + 2) % NSTG);
        else CP_COMMIT();

        const char* As_ = smem + stg * STAGEB;
        const char* Bs_ = As_ + TILEB;

#pragma unroll
        for (int kk = 0; kk < 4; kk++) {
            uint32_t af[4][4];
#pragma unroll
            for (int mi = 0; mi < 4; mi++) {
                const int row = wm * 64 + mi * 16 + ar;
                const uint32_t a = smem_u32(As_ + row * ROWB + (kk * 8 + ac4) * 4);
                asm volatile("ldmatrix.sync.aligned.m8n8.x4.shared.b16 {%0,%1,%2,%3}, [%4];"
                             : "=r"(af[mi][0]), "=r"(af[mi][1]), "=r"(af[mi][2]), "=r"(af[mi][3])
                             : "r"(a) : "memory");
            }
            uint32_t bfr[2][4];
#pragma unroll
            for (int nb = 0; nb < 2; nb++) {
                const int nrow = wn * 32 + nb * 16 + br;
                const uint32_t a = smem_u32(Bs_ + nrow * ROWB + (kk * 8 + bc4) * 4);
                asm volatile("ldmatrix.sync.aligned.m8n8.x4.shared.b16 {%0,%1,%2,%3}, [%4];"
                             : "=r"(bfr[nb][0]), "=r"(bfr[nb][1]), "=r"(bfr[nb][2]), "=r"(bfr[nb][3])
                             : "r"(a) : "memory");
            }
#pragma unroll
            for (int mi = 0; mi < 4; mi++)
#pragma unroll
                for (int ni = 0; ni < 4; ni++) {
                    const uint32_t b0 = bfr[ni >> 1][(ni & 1) * 2];
                    const uint32_t b1 = bfr[ni >> 1][(ni & 1) * 2 + 1];
                    MMA_TF32(acc[mi][ni], af[mi][0], af[mi][1], af[mi][2], af[mi][3], b0, b1);
                }
        }
    }

    float* Y = BATCHED ? ((zA == 0) ? g_Q : (zA == 1) ? g_K : g_V) : Yp;
    float* stg_ = (float*)smem;
    const int gid = lane >> 2, tid2 = (lane & 3) * 2;
#pragma unroll 1
    for (int cb = 0; cb < 4; cb++) {
        __syncthreads();
        if (wn == cb) {
#pragma unroll
            for (int mi = 0; mi < 4; mi++)
#pragma unroll
                for (int ni = 0; ni < 4; ni++) {
                    const int r = wm * 64 + mi * 16 + gid;
                    const int c = ni * 8 + tid2;
                    stg_[r * 36 + c]            = acc[mi][ni][0];
                    stg_[r * 36 + c + 1]        = acc[mi][ni][1];
                    stg_[(r + 8) * 36 + c]      = acc[mi][ni][2];
                    stg_[(r + 8) * 36 + c + 1]  = acc[mi][ni][3];
                }
        }
        __syncthreads();
        for (int e = t; e < 1024; e += 256) {
            const int r = e >> 3, c4 = (e & 7) * 4;
            float4 val = *(const float4*)&stg_[r * 36 + c4];
            const int n = n0 + cb * 32 + c4;
            const int m = m0 + r;
            if (!BATCHED) {
                *(float4*)(Y + (size_t)m * EMB + n) = val;
            } else {
                const int b = m >> 11, tt = m & 2047;
                const int h = n >> 6, d = n & 63;
                *(float4*)(Y + ((size_t)(b * NH + h) * T_SEQ + tt) * DH + d) = val;
            }
        }
    }
}

// ---------------------------------------------------------------------------
// tf32 flash attention (causal), cp.async double-buffered K/V staging.
// K/V staged as raw fp32; tensor core reads the 19 tf32 bits (truncation).
// Q rna-converted (one-time). Epilogue writes tf32 into g_A2[z=0].
// ---------------------------------------------------------------------------
#define KST 68
#define VST 72
#define PST 68
#define KBUFF (64 * KST)             // floats per K buffer
#define VBUFF (64 * VST)
#define SMEM_ATTN ((2 * KBUFF + 2 * VBUFF + 8 * 16 * PST) * 4)   // 106496

__global__ void __launch_bounds__(256, 2) attn_tc_kernel()
{
    extern __shared__ float sm[];
    float* Kb[2] = { sm, sm + KBUFF };
    float* Vb[2] = { sm + 2 * KBUFF, sm + 2 * KBUFF + VBUFF };
    float* Pw_base = sm + 2 * KBUFF + 2 * VBUFF;

    const int bh = blockIdx.y;
    const int qt = (int)gridDim.x - 1 - (int)blockIdx.x;
    const int q0 = qt * 128;
    const int t = threadIdx.x;
    const int w = t >> 5, lane = t & 31;
    const int g = lane >> 2, tig = lane & 3;

    const float* Qg = g_Q + (size_t)bh * T_SEQ * DH;
    const float* Kg = g_K + (size_t)bh * T_SEQ * DH;
    const float* Vg = g_V + (size_t)bh * T_SEQ * DH;

    // ---- stage Q (x0.125, rna tf32) into sm[0 .. 128*KST) (= both K buffers)
#pragma unroll
    for (int qq = 0; qq < 8; qq++) {
        const int idx = t + qq * 256;
        const int row = idx >> 4, c4 = (idx & 15) << 2;
        float4 f = *(const float4*)(Qg + (size_t)(q0 + row) * DH + c4);
        uint4 u;
        u.x = f2tf32(f.x * 0.125f); u.y = f2tf32(f.y * 0.125f);
        u.z = f2tf32(f.z * 0.125f); u.w = f2tf32(f.w * 0.125f);
        *(uint4*)(sm + row * KST + c4) = u;
    }
    __syncthreads();

    uint32_t qf[8][4];
    {
        const float* Qw = sm + (w * 16) * KST;
#pragma unroll
        for (int kc = 0; kc < 8; kc++) {
            qf[kc][0] = *(const uint32_t*)&Qw[g * KST + kc * 8 + tig];
            qf[kc][1] = *(const uint32_t*)&Qw[(g + 8) * KST + kc * 8 + tig];
            qf[kc][2] = *(const uint32_t*)&Qw[g * KST + kc * 8 + tig + 4];
            qf[kc][3] = *(const uint32_t*)&Qw[(g + 8) * KST + kc * 8 + tig + 4];
        }
    }
    __syncthreads();   // Q reads done before cp.async overwrites the region

    // per-thread staging coords: 4 segs K + 4 segs V (16B each)
    const int srow = t >> 4, sc4 = (t & 15) << 2;   // base: rows t>>4 + 16*qq
    auto stage_tile = [&](int kt, int buf) {
        const int k0 = kt * 64;
#pragma unroll
        for (int qq = 0; qq < 4; qq++) {
            const int row = srow + qq * 16;
            const uint32_t dk = smem_u32(Kb[buf] + row * KST + sc4);
            const uint32_t dv = smem_u32(Vb[buf] + row * VST + sc4);
            CP16(dk, Kg + (size_t)(k0 + row) * DH + sc4);
            CP16(dv, Vg + (size_t)(k0 + row) * DH + sc4);
        }
        CP_COMMIT();
    };

    float o[8][4];
#pragma unroll
    for (int nt = 0; nt < 8; nt++)
#pragma unroll
        for (int j = 0; j < 4; j++) o[nt][j] = 0.f;
    float m0 = -1e30f, m1 = -1e30f, l0 = 0.f, l1 = 0.f;

    float* Pw = Pw_base + w * 16 * PST;
    const int ktmax = 2 * qt + 1;

    stage_tile(0, 0);

    for (int kt = 0; kt <= ktmax; kt++) {
        const int buf = kt & 1;
        if (kt < ktmax) stage_tile(kt + 1, buf ^ 1);
        else CP_COMMIT();
        CP_WAIT1();
        __syncthreads();

        const float* Ks = Kb[buf];
        const float* Vs = Vb[buf];
        const int k0 = kt * 64;

        float s[8][4];
#pragma unroll
        for (int nt = 0; nt < 8; nt++) {
            s[nt][0] = 0.f; s[nt][1] = 0.f; s[nt][2] = 0.f; s[nt][3] = 0.f;
            const float* Kr = Ks + (nt * 8 + g) * KST + tig;
#pragma unroll
            for (int kc = 0; kc < 8; kc++) {
                const uint32_t b0 = *(const uint32_t*)&Kr[kc * 8];
                const uint32_t b1 = *(const uint32_t*)&Kr[kc * 8 + 4];
                MMA_TF32(s[nt], qf[kc][0], qf[kc][1], qf[kc][2], qf[kc][3], b0, b1);
            }
        }

        if (kt >= 2 * qt) {
            const int r0 = q0 + w * 16 + g, r1 = r0 + 8;
#pragma unroll
            for (int nt = 0; nt < 8; nt++) {
                const int c0 = k0 + nt * 8 + 2 * tig;
                if (c0     > r0) s[nt][0] = -1e30f;
                if (c0 + 1 > r0) s[nt][1] = -1e30f;
                if (c0     > r1) s[nt][2] = -1e30f;
                if (c0 + 1 > r1) s[nt][3] = -1e30f;
            }
        }

        float rm0 = -1e30f, rm1 = -1e30f;
#pragma unroll
        for (int nt = 0; nt < 8; nt++) {
            rm0 = fmaxf(rm0, fmaxf(s[nt][0], s[nt][1]));
            rm1 = fmaxf(rm1, fmaxf(s[nt][2], s[nt][3]));
        }
        rm0 = fmaxf(rm0, __shfl_xor_sync(0xffffffffu, rm0, 1));
        rm0 = fmaxf(rm0, __shfl_xor_sync(0xffffffffu, rm0, 2));
        rm1 = fmaxf(rm1, __shfl_xor_sync(0xffffffffu, rm1, 1));
        rm1 = fmaxf(rm1, __shfl_xor_sync(0xffffffffu, rm1, 2));
        const float mn0 = fmaxf(m0, rm0), mn1 = fmaxf(m1, rm1);
        const float a0 = __expf(m0 - mn0), a1 = __expf(m1 - mn1);
        float rs0 = 0.f, rs1 = 0.f;
#pragma unroll
        for (int nt = 0; nt < 8; nt++) {
            s[nt][0] = __expf(s[nt][0] - mn0); rs0 += s[nt][0];
            s[nt][1] = __expf(s[nt][1] - mn0); rs0 += s[nt][1];
            s[nt][2] = __expf(s[nt][2] - mn1); rs1 += s[nt][2];
            s[nt][3] = __expf(s[nt][3] - mn1); rs1 += s[nt][3];
        }
        rs0 += __shfl_xor_sync(0xffffffffu, rs0, 1);
        rs0 += __shfl_xor_sync(0xffffffffu, rs0, 2);
        rs1 += __shfl_xor_sync(0xffffffffu, rs1, 1);
        rs1 += __shfl_xor_sync(0xffffffffu, rs1, 2);
        l0 = l0 * a0 + rs0; m0 = mn0;
        l1 = l1 * a1 + rs1; m1 = mn1;
#pragma unroll
        for (int nt = 0; nt < 8; nt++) {
            o[nt][0] *= a0; o[nt][1] *= a0;
            o[nt][2] *= a1; o[nt][3] *= a1;
        }

#pragma unroll
        for (int nt = 0; nt < 8; nt++) {
            *(float2*)&Pw[g * PST + nt * 8 + 2 * tig]       = make_float2(s[nt][0], s[nt][1]);
            *(float2*)&Pw[(g + 8) * PST + nt * 8 + 2 * tig] = make_float2(s[nt][2], s[nt][3]);
        }
        __syncwarp();

#pragma unroll
        for (int kc = 0; kc < 8; kc++) {
            const uint32_t pa0 = f2tf32(Pw[g * PST + kc * 8 + tig]);
            const uint32_t pa1 = f2tf32(Pw[(g + 8) * PST + kc * 8 + tig]);
            const uint32_t pa2 = f2tf32(Pw[g * PST + kc * 8 + tig + 4]);
            const uint32_t pa3 = f2tf32(Pw[(g + 8) * PST + kc * 8 + tig + 4]);
            const float* Vr0 = Vs + (kc * 8 + tig) * VST + g;
            const float* Vr1 = Vs + (kc * 8 + tig + 4) * VST + g;
#pragma unroll
            for (int nt = 0; nt < 8; nt++) {
                const uint32_t b0 = *(const uint32_t*)&Vr0[nt * 8];
                const uint32_t b1 = *(const uint32_t*)&Vr1[nt * 8];
                MMA_TF32(o[nt], pa0, pa1, pa2, pa3, b0, b1);
            }
        }
        __syncthreads();   // reads done before next iteration's cp.async writes
    }

    const int b = bh >> 4, h = bh & 15;
    const int r0 = q0 + w * 16 + g;
    const float inv0 = 1.0f / l0, inv1 = 1.0f / l1;
    uint32_t* row0 = g_A2 + (size_t)(b * T_SEQ + r0) * EMB;
    uint32_t* row1 = g_A2 + (size_t)(b * T_SEQ + r0 + 8) * EMB;
#pragma unroll
    for (int nt = 0; nt < 8; nt++) {
        const int col = h * DH + nt * 8 + 2 * tig;
        uint2 u0, u1;
        u0.x = f2tf32(o[nt][0] * inv0); u0.y = f2tf32(o[nt][1] * inv0);
        u1.x = f2tf32(o[nt][2] * inv1); u1.y = f2tf32(o[nt][3] * inv1);
        *(uint2*)&row0[col] = u0;
        *(uint2*)&row1[col] = u1;
    }
}

extern "C" void kernel_launch(void* const* d_in, const int* in_sizes, int n_in,
                              void* d_out, int out_size)
{
    (void)in_sizes; (void)n_in; (void)out_size;
    const float* q  = (const float*)d_in[0];
    const float* k  = (const float*)d_in[1];
    const float* v  = (const float*)d_in[2];
    const float* Wq = (const float*)d_in[3];
    const float* Wk = (const float*)d_in[4];
    const float* Wv = (const float*)d_in[5];
    const float* Wo = (const float*)d_in[6];
    float* out = (float*)d_out;

    static bool attr_set = false;
    if (!attr_set) {
        cudaFuncSetAttribute(attn_tc_kernel, cudaFuncAttributeMaxDynamicSharedMemorySize, SMEM_ATTN);
        cudaFuncSetAttribute(gemm_kernel<0>, cudaFuncAttributeMaxDynamicSharedMemorySize, SMEM_GEMM);
        cudaFuncSetAttribute(gemm_kernel<1>, cudaFuncAttributeMaxDynamicSharedMemorySize, SMEM_GEMM);
        attr_set = true;
    }

    conv_act<<<12288, 256>>>(q, k, v);
    conv_wgt4<<<4096, 256>>>(Wq, Wk, Wv, Wo);
    gemm_kernel<1><<<dim3(EMB / 128, NTOK / 128, 3), 256, SMEM_GEMM>>>(nullptr);

    attn_tc_kernel<<<dim3(T_SEQ / 128, BATCH * NH), 256, SMEM_ATTN>>>();

    gemm_kernel<0><<<dim3(EMB / 128, NTOK / 128), 256, SMEM_GEMM>>>(out);
}

// round 12
// speedup vs baseline: 1.0654x; 1.0654x over previous
#include <cuda_runtime.h>
#include <cuda_bf16.h>
#include <cstdint>
#include <math.h>

#define T_SEQ 2048
#define BATCH 2
#define EMB   1024
#define NH    16
#define DH    64
#define NTOK  (BATCH * T_SEQ)

__device__ float g_Q[(size_t)NTOK * EMB];
__device__ float g_K[(size_t)NTOK * EMB];
__device__ float g_V[(size_t)NTOK * EMB];
__device__ uint32_t g_A2[(size_t)3 * NTOK * EMB];   // tf32 activations
__device__ uint32_t g_B2[(size_t)4 * EMB  * EMB];   // tf32 weights (q,k,v,o)

__device__ __forceinline__ uint32_t smem_u32(const void* p) {
    uint32_t a;
    asm("{ .reg .u64 t; cvta.to.shared.u64 t, %1; cvt.u32.u64 %0, t; }" : "=r"(a) : "l"(p));
    return a;
}
#define CP16(dst, src) \
    asm volatile("cp.async.cg.shared.global [%0], [%1], 16;" :: "r"(dst), "l"(src) : "memory")
#define CP_COMMIT() asm volatile("cp.async.commit_group;" ::: "memory")
#define CP_WAIT1()  asm volatile("cp.async.wait_group 1;" ::: "memory")

__device__ __forceinline__ uint32_t f2tf32(float x) {
    uint32_t u;
    asm("cvt.rna.tf32.f32 %0, %1;" : "=r"(u) : "f"(x));
    return u;
}
#define MMA_TF32(c, a0, a1, a2, a3, b0, b1)                                 \
    asm volatile("mma.sync.aligned.m16n8k8.row.col.f32.tf32.tf32.f32 "     \
        "{%0,%1,%2,%3}, {%4,%5,%6,%7}, {%8,%9}, {%0,%1,%2,%3};"            \
        : "+f"((c)[0]), "+f"((c)[1]), "+f"((c)[2]), "+f"((c)[3])           \
        : "r"(a0), "r"(a1), "r"(a2), "r"(a3), "r"(b0), "r"(b1))
#define LDSM_X4(r, addr)                                                    \
    asm volatile("ldmatrix.sync.aligned.m8n8.x4.shared.b16 {%0,%1,%2,%3}, [%4];" \
        : "=r"((r)[0]), "=r"((r)[1]), "=r"((r)[2]), "=r"((r)[3])           \
        : "r"(addr) : "memory")

// ---------------------------------------------------------------------------
// tf32 converts: acts (q,k,v batched), weights (q,k,v,o batched).
// ---------------------------------------------------------------------------
__global__ void conv_act(const float* __restrict__ q, const float* __restrict__ k,
                         const float* __restrict__ v)
{
    const int z = blockIdx.x >> 12;
    const float* X = (z == 0) ? q : (z == 1) ? k : v;
    uint32_t* Y = g_A2 + (size_t)z * NTOK * EMB;
    const int idx = (blockIdx.x & 4095) * 256 + threadIdx.x;
    float4 f = ((const float4*)X)[idx];
    uint4 u;
    u.x = f2tf32(f.x); u.y = f2tf32(f.y); u.z = f2tf32(f.z); u.w = f2tf32(f.w);
    ((uint4*)Y)[idx] = u;
}

__global__ void conv_wgt4(const float* __restrict__ Wq, const float* __restrict__ Wk,
                          const float* __restrict__ Wv, const float* __restrict__ Wo)
{
    const int z = blockIdx.x >> 10;
    const float* W = (z == 0) ? Wq : (z == 1) ? Wk : (z == 2) ? Wv : Wo;
    uint32_t* Y = g_B2 + (size_t)z * EMB * EMB;
    const int idx = (blockIdx.x & 1023) * 256 + threadIdx.x;
    float4 f = ((const float4*)W)[idx];
    uint4 u;
    u.x = f2tf32(f.x); u.y = f2tf32(f.y); u.z = f2tf32(f.z); u.w = f2tf32(f.w);
    ((uint4*)Y)[idx] = u;
}

// ---------------------------------------------------------------------------
// tf32 mma.sync GEMM (unchanged, proven): 128x128, BKC=32, 3-stage cp.async.
// BATCHED=1: z = blockIdx.z (QKV). BATCHED=0: A z=0, B z=3 (O-projection).
// ---------------------------------------------------------------------------
#define BKC 32
#define NCH (EMB / BKC)
#define ROWB 144
#define TILEB (128 * ROWB)
#define STAGEB (2 * TILEB)
#define NSTG 3
#define SMEM_GEMM (NSTG * STAGEB)

template <int BATCHED>
__global__ void __launch_bounds__(256, 2) gemm_kernel(float* __restrict__ Yp)
{
    extern __shared__ char smem[];
    const int t = threadIdx.x;
    const int wid = t >> 5, lane = t & 31;
    const int wm = wid & 1;
    const int wn = wid >> 1;
    const int m0 = blockIdx.y * 128;
    const int n0 = blockIdx.x * 128;
    const int zA = BATCHED ? blockIdx.z : 0;
    const int zB = BATCHED ? blockIdx.z : 3;

    const uint32_t* Ag = g_A2 + (size_t)zA * NTOK * EMB + (size_t)m0 * EMB;
    const uint32_t* Bg = g_B2 + (size_t)zB * EMB  * EMB + (size_t)n0 * EMB;

    float acc[4][4][4];
#pragma unroll
    for (int mi = 0; mi < 4; mi++)
#pragma unroll
        for (int ni = 0; ni < 4; ni++)
#pragma unroll
            for (int d = 0; d < 4; d++) acc[mi][ni][d] = 0.f;

    auto load_stage = [&](int ch, int stg) {
        char* base = smem + stg * STAGEB;
        const size_t koff = (size_t)ch * BKC;
#pragma unroll
        for (int q = 0; q < 8; q++) {
            const int s = t + q * 256;
            const int tile = s >> 10;
            const int r = (s >> 3) & 127;
            const int ks = s & 7;
            const uint32_t dst = smem_u32(base + tile * TILEB + r * ROWB + ks * 16);
            const uint32_t* src = (tile ? Bg : Ag) + (size_t)r * EMB + koff + ks * 4;
            CP16(dst, src);
        }
        CP_COMMIT();
    };

    load_stage(0, 0);
    load_stage(1, 1);

    const int ar = (lane & 7) + ((lane >> 3) & 1) * 8;
    const int ac4 = ((lane >> 4) & 1) * 4;
    const int br = (lane & 7) + ((lane >> 4) & 1) * 8;
    const int bc4 = ((lane >> 3) & 1) * 4;

    for (int ch = 0; ch < NCH; ch++) {
        const int stg = ch % NSTG;
        CP_WAIT1();
        __syncthreads();
        if (ch + 2 < NCH) load_stage(ch + 2, (ch + 2) % NSTG);
        else CP_COMMIT();

        const char* As_ = smem + stg * STAGEB;
        const char* Bs_ = As_ + TILEB;

#pragma unroll
        for (int kk = 0; kk < 4; kk++) {
            uint32_t af[4][4];
#pragma unroll
            for (int mi = 0; mi < 4; mi++) {
                const int row = wm * 64 + mi * 16 + ar;
                LDSM_X4(af[mi], smem_u32(As_ + row * ROWB + (kk * 8 + ac4) * 4));
            }
            uint32_t bfr[2][4];
#pragma unroll
            for (int nb = 0; nb < 2; nb++) {
                const int nrow = wn * 32 + nb * 16 + br;
                LDSM_X4(bfr[nb], smem_u32(Bs_ + nrow * ROWB + (kk * 8 + bc4) * 4));
            }
#pragma unroll
            for (int mi = 0; mi < 4; mi++)
#pragma unroll
                for (int ni = 0; ni < 4; ni++) {
                    const uint32_t b0 = bfr[ni >> 1][(ni & 1) * 2];
                    const uint32_t b1 = bfr[ni >> 1][(ni & 1) * 2 + 1];
                    MMA_TF32(acc[mi][ni], af[mi][0], af[mi][1], af[mi][2], af[mi][3], b0, b1);
                }
        }
    }

    float* Y = BATCHED ? ((zA == 0) ? g_Q : (zA == 1) ? g_K : g_V) : Yp;
    float* stg_ = (float*)smem;
    const int gid = lane >> 2, tid2 = (lane & 3) * 2;
#pragma unroll 1
    for (int cb = 0; cb < 4; cb++) {
        __syncthreads();
        if (wn == cb) {
#pragma unroll
            for (int mi = 0; mi < 4; mi++)
#pragma unroll
                for (int ni = 0; ni < 4; ni++) {
                    const int r = wm * 64 + mi * 16 + gid;
                    const int c = ni * 8 + tid2;
                    stg_[r * 36 + c]            = acc[mi][ni][0];
                    stg_[r * 36 + c + 1]        = acc[mi][ni][1];
                    stg_[(r + 8) * 36 + c]      = acc[mi][ni][2];
                    stg_[(r + 8) * 36 + c + 1]  = acc[mi][ni][3];
                }
        }
        __syncthreads();
        for (int e = t; e < 1024; e += 256) {
            const int r = e >> 3, c4 = (e & 7) * 4;
            float4 val = *(const float4*)&stg_[r * 36 + c4];
            const int n = n0 + cb * 32 + c4;
            const int m = m0 + r;
            if (!BATCHED) {
                *(float4*)(Y + (size_t)m * EMB + n) = val;
            } else {
                const int b = m >> 11, tt = m & 2047;
                const int h = n >> 6, d = n & 63;
                *(float4*)(Y + ((size_t)(b * NH + h) * T_SEQ + tt) * DH + d) = val;
            }
        }
    }
}

// ---------------------------------------------------------------------------
// tf32 flash attention (causal). R10 staging (LDG->rna cvt->STS, measured-good)
// + ldmatrix.x4 K-fragment loads (GEMM-proven B addressing; K is [key][d]
// row-major, stride 272B keeps ldmatrix rows on distinct 16B banks).
// Epilogue writes tf32 into g_A2[z=0] for the O-GEMM.
// ---------------------------------------------------------------------------
#define KST 68
#define VST 72
#define PST 68
#define SMEM_ATTN ((64 * KST + 64 * VST + 8 * 16 * PST) * 4)

__global__ void __launch_bounds__(256, 2) attn_tc_kernel()
{
    extern __shared__ float sm[];
    float* Ks = sm;
    float* Vs = sm + 64 * KST;
    float* Pw_base = sm + 64 * KST + 64 * VST;

    const int bh = blockIdx.y;
    const int qt = (int)gridDim.x - 1 - (int)blockIdx.x;
    const int q0 = qt * 128;
    const int t = threadIdx.x;
    const int w = t >> 5, lane = t & 31;
    const int g = lane >> 2, tig = lane & 3;

    const float* Qg = g_Q + (size_t)bh * T_SEQ * DH;
    const float* Kg = g_K + (size_t)bh * T_SEQ * DH;
    const float* Vg = g_V + (size_t)bh * T_SEQ * DH;

    // ---- stage Q (x0.125, rna tf32) into sm[0..128*KST) ----
#pragma unroll
    for (int qq = 0; qq < 8; qq++) {
        const int idx = t + qq * 256;
        const int row = idx >> 4, c4 = (idx & 15) << 2;
        float4 f = *(const float4*)(Qg + (size_t)(q0 + row) * DH + c4);
        uint4 u;
        u.x = f2tf32(f.x * 0.125f); u.y = f2tf32(f.y * 0.125f);
        u.z = f2tf32(f.z * 0.125f); u.w = f2tf32(f.w * 0.125f);
        *(uint4*)(sm + row * KST + c4) = u;
    }
    __syncthreads();

    uint32_t qf[8][4];
    {
        const float* Qw = sm + (w * 16) * KST;
#pragma unroll
        for (int kc = 0; kc < 8; kc++) {
            qf[kc][0] = *(const uint32_t*)&Qw[g * KST + kc * 8 + tig];
            qf[kc][1] = *(const uint32_t*)&Qw[(g + 8) * KST + kc * 8 + tig];
            qf[kc][2] = *(const uint32_t*)&Qw[g * KST + kc * 8 + tig + 4];
            qf[kc][3] = *(const uint32_t*)&Qw[(g + 8) * KST + kc * 8 + tig + 4];
        }
    }
    __syncthreads();   // Q reads done before K/V staging overwrites

    float o[8][4];
#pragma unroll
    for (int nt = 0; nt < 8; nt++)
#pragma unroll
        for (int j = 0; j < 4; j++) o[nt][j] = 0.f;
    float m0 = -1e30f, m1 = -1e30f, l0 = 0.f, l1 = 0.f;

    float* Pw = Pw_base + w * 16 * PST;

    // ldmatrix lane coords for K (B-operand): same as GEMM's B pattern
    const int kbr = (lane & 7) + ((lane >> 4) & 1) * 8;   // row within 16-key block
    const int kbc4 = ((lane >> 3) & 1) * 4;               // tf32 col sel

    const int ktmax = 2 * qt + 1;
    for (int kt = 0; kt <= ktmax; kt++) {
        const int k0 = kt * 64;
#pragma unroll
        for (int qq = 0; qq < 4; qq++) {
            const int idx = t + qq * 256;
            const int row = idx >> 4, c4 = (idx & 15) << 2;
            float4 fk = *(const float4*)(Kg + (size_t)(k0 + row) * DH + c4);
            float4 fv = *(const float4*)(Vg + (size_t)(k0 + row) * DH + c4);
            uint4 uk, uv;
            uk.x = f2tf32(fk.x); uk.y = f2tf32(fk.y); uk.z = f2tf32(fk.z); uk.w = f2tf32(fk.w);
            uv.x = f2tf32(fv.x); uv.y = f2tf32(fv.y); uv.z = f2tf32(fv.z); uv.w = f2tf32(fv.w);
            *(uint4*)(Ks + row * KST + c4) = uk;
            *(uint4*)(Vs + row * VST + c4) = uv;
        }
        __syncthreads();

        // ---- S = (Q/8) @ K^T via ldmatrix.x4 K fragments ----
        float s[8][4];
#pragma unroll
        for (int nt = 0; nt < 8; nt++) {
            s[nt][0] = 0.f; s[nt][1] = 0.f; s[nt][2] = 0.f; s[nt][3] = 0.f;
        }
#pragma unroll
        for (int kk = 0; kk < 8; kk++) {         // k8 steps over d
            uint32_t bfr[4][4];
#pragma unroll
            for (int ntb = 0; ntb < 4; ntb++) {  // 16-key blocks
                const int nrow = ntb * 16 + kbr;
                LDSM_X4(bfr[ntb], smem_u32(Ks + nrow * KST + kk * 8 + kbc4));
            }
#pragma unroll
            for (int nt = 0; nt < 8; nt++) {
                const uint32_t b0 = bfr[nt >> 1][(nt & 1) * 2];
                const uint32_t b1 = bfr[nt >> 1][(nt & 1) * 2 + 1];
                MMA_TF32(s[nt], qf[kk][0], qf[kk][1], qf[kk][2], qf[kk][3], b0, b1);
            }
        }

        if (kt >= 2 * qt) {
            const int r0 = q0 + w * 16 + g, r1 = r0 + 8;
#pragma unroll
            for (int nt = 0; nt < 8; nt++) {
                const int c0 = k0 + nt * 8 + 2 * tig;
                if (c0     > r0) s[nt][0] = -1e30f;
                if (c0 + 1 > r0) s[nt][1] = -1e30f;
                if (c0     > r1) s[nt][2] = -1e30f;
                if (c0 + 1 > r1) s[nt][3] = -1e30f;
            }
        }

        float rm0 = -1e30f, rm1 = -1e30f;
#pragma unroll
        for (int nt = 0; nt < 8; nt++) {
            rm0 = fmaxf(rm0, fmaxf(s[nt][0], s[nt][1]));
            rm1 = fmaxf(rm1, fmaxf(s[nt][2], s[nt][3]));
        }
        rm0 = fmaxf(rm0, __shfl_xor_sync(0xffffffffu, rm0, 1));
        rm0 = fmaxf(rm0, __shfl_xor_sync(0xffffffffu, rm0, 2));
        rm1 = fmaxf(rm1, __shfl_xor_sync(0xffffffffu, rm1, 1));
        rm1 = fmaxf(rm1, __shfl_xor_sync(0xffffffffu, rm1, 2));
        const float mn0 = fmaxf(m0, rm0), mn1 = fmaxf(m1, rm1);
        const float a0 = __expf(m0 - mn0), a1 = __expf(m1 - mn1);
        float rs0 = 0.f, rs1 = 0.f;
#pragma unroll
        for (int nt = 0; nt < 8; nt++) {
            s[nt][0] = __expf(s[nt][0] - mn0); rs0 += s[nt][0];
            s[nt][1] = __expf(s[nt][1] - mn0); rs0 += s[nt][1];
            s[nt][2] = __expf(s[nt][2] - mn1); rs1 += s[nt][2];
            s[nt][3] = __expf(s[nt][3] - mn1); rs1 += s[nt][3];
        }
        rs0 += __shfl_xor_sync(0xffffffffu, rs0, 1);
        rs0 += __shfl_xor_sync(0xffffffffu, rs0, 2);
        rs1 += __shfl_xor_sync(0xffffffffu, rs1, 1);
        rs1 += __shfl_xor_sync(0xffffffffu, rs1, 2);
        l0 = l0 * a0 + rs0; m0 = mn0;
        l1 = l1 * a1 + rs1; m1 = mn1;
#pragma unroll
        for (int nt = 0; nt < 8; nt++) {
            o[nt][0] *= a0; o[nt][1] *= a0;
            o[nt][2] *= a1; o[nt][3] *= a1;
        }

#pragma unroll
        for (int nt = 0; nt < 8; nt++) {
            *(float2*)&Pw[g * PST + nt * 8 + 2 * tig]       = make_float2(s[nt][0], s[nt][1]);
            *(float2*)&Pw[(g + 8) * PST + nt * 8 + 2 * tig] = make_float2(s[nt][2], s[nt][3]);
        }
        __syncwarp();

#pragma unroll
        for (int kc = 0; kc < 8; kc++) {
            const uint32_t pa0 = f2tf32(Pw[g * PST + kc * 8 + tig]);
            const uint32_t pa1 = f2tf32(Pw[(g + 8) * PST + kc * 8 + tig]);
            const uint32_t pa2 = f2tf32(Pw[g * PST + kc * 8 + tig + 4]);
            const uint32_t pa3 = f2tf32(Pw[(g + 8) * PST + kc * 8 + tig + 4]);
            const float* Vr0 = Vs + (kc * 8 + tig) * VST + g;
            const float* Vr1 = Vs + (kc * 8 + tig + 4) * VST + g;
#pragma unroll
            for (int nt = 0; nt < 8; nt++) {
                const uint32_t b0 = *(const uint32_t*)&Vr0[nt * 8];
                const uint32_t b1 = *(const uint32_t*)&Vr1[nt * 8];
                MMA_TF32(o[nt], pa0, pa1, pa2, pa3, b0, b1);
            }
        }
        __syncthreads();
    }

    const int b = bh >> 4, h = bh & 15;
    const int r0 = q0 + w * 16 + g;
    const float inv0 = 1.0f / l0, inv1 = 1.0f / l1;
    uint32_t* row0 = g_A2 + (size_t)(b * T_SEQ + r0) * EMB;
    uint32_t* row1 = g_A2 + (size_t)(b * T_SEQ + r0 + 8) * EMB;
#pragma unroll
    for (int nt = 0; nt < 8; nt++) {
        const int col = h * DH + nt * 8 + 2 * tig;
        uint2 u0, u1;
        u0.x = f2tf32(o[nt][0] * inv0); u0.y = f2tf32(o[nt][1] * inv0);
        u1.x = f2tf32(o[nt][2] * inv1); u1.y = f2tf32(o[nt][3] * inv1);
        *(uint2*)&row0[col] = u0;
        *(uint2*)&row1[col] = u1;
    }
}

extern "C" void kernel_launch(void* const* d_in, const int* in_sizes, int n_in,
                              void* d_out, int out_size)
{
    (void)in_sizes; (void)n_in; (void)out_size;
    const float* q  = (const float*)d_in[0];
    const float* k  = (const float*)d_in[1];
    const float* v  = (const float*)d_in[2];
    const float* Wq = (const float*)d_in[3];
    const float* Wk = (const float*)d_in[4];
    const float* Wv = (const float*)d_in[5];
    const float* Wo = (const float*)d_in[6];
    float* out = (float*)d_out;

    static bool attr_set = false;
    if (!attr_set) {
        cudaFuncSetAttribute(attn_tc_kernel, cudaFuncAttributeMaxDynamicSharedMemorySize, SMEM_ATTN);
        cudaFuncSetAttribute(gemm_kernel<0>, cudaFuncAttributeMaxDynamicSharedMemorySize, SMEM_GEMM);
        cudaFuncSetAttribute(gemm_kernel<1>, cudaFuncAttributeMaxDynamicSharedMemorySize, SMEM_GEMM);
        attr_set = true;
    }

    conv_act<<<12288, 256>>>(q, k, v);
    conv_wgt4<<<4096, 256>>>(Wq, Wk, Wv, Wo);
    gemm_kernel<1><<<dim3(EMB / 128, NTOK / 128, 3), 256, SMEM_GEMM>>>(nullptr);

    attn_tc_kernel<<<dim3(T_SEQ / 128, BATCH * NH), 256, SMEM_ATTN>>>();

    gemm_kernel<0><<<dim3(EMB / 128, NTOK / 128), 256, SMEM_GEMM>>>(out);
}